// round 5
// baseline (speedup 1.0000x reference)
#include <cuda_runtime.h>
#include <cuda_bf16.h>

// Problem constants
#define NN 100000
#define EE 1600000
#define C  128      // IN_C = H1 = H2 = 128
#define OC 64

// Scratch (allocation-free rule: __device__ globals)
__device__ float g_deg[NN];
__device__ float g_dinv[NN];
__device__ float g_bufH[(size_t)NN * C];   // hs = (A*W)*dinv[row]
__device__ float g_bufG[(size_t)NN * C];   // agg accumulator
__device__ float g_bufX[(size_t)NN * C];   // relu(layer1) output

// ---------------------------------------------------------------------------
// degree / norm.  edge_index is int32 (JAX x64 disabled): ei[0..e) = row,
// ei[e..2e) = col.
// ---------------------------------------------------------------------------
__global__ void deg_init_kernel(float* __restrict__ deg, int n) {
    int i = blockIdx.x * blockDim.x + threadIdx.x;
    if (i < n) deg[i] = 1.0f;   // self-loop
}

__global__ void deg_accum_kernel(const int* __restrict__ ei,
                                 float* __restrict__ deg, int e, int n) {
    int i = blockIdx.x * blockDim.x + threadIdx.x;
    if (i < e) {
        int c = ei[e + i];           // col = ei[1][i]
        if ((unsigned)c < (unsigned)n) atomicAdd(&deg[c], 1.0f);
    }
}

__global__ void dinv_kernel(const float* __restrict__ deg,
                            float* __restrict__ dinv, int n) {
    int i = blockIdx.x * blockDim.x + threadIdx.x;
    if (i < n) dinv[i] = rsqrtf(deg[i]);   // deg >= 1 always (self-loop)
}

// ---------------------------------------------------------------------------
// GEMM: [n x 128] @ [128 x 128], epilogue writes
//   hs[row]  = acc * dinv[row]
//   agg[row] = acc * dinv[row]^2   (self-loop contribution pre-seeded)
// Block: 256 threads, tile 64 rows x 128 cols. Thread (ty=t/32, tx=t%32)
// computes 8 rows x 4 cols.
// ---------------------------------------------------------------------------
__global__ __launch_bounds__(256) void gemm_scaled_kernel(
    const float* __restrict__ A, const float* __restrict__ W,
    const float* __restrict__ dinv,
    float* __restrict__ hs, float* __restrict__ agg, int nrows)
{
    __shared__ float As[64][C];    // 32 KB
    __shared__ float Ws[16][C];    //  8 KB
    int t  = threadIdx.x;
    int tx = t & 31;
    int ty = t >> 5;
    int row0 = blockIdx.x * 64;

    // stage A tile (64x128) : 2048 float4, 8 per thread, coalesced
    for (int i = t; i < 64 * 32; i += 256) {
        int r = i >> 5, c4 = i & 31;
        int gr = row0 + r;
        float4 v = (gr < nrows)
                     ? reinterpret_cast<const float4*>(A)[(size_t)gr * 32 + c4]
                     : make_float4(0.f, 0.f, 0.f, 0.f);
        reinterpret_cast<float4*>(&As[r][0])[c4] = v;
    }

    float acc[8][4];
    #pragma unroll
    for (int r = 0; r < 8; r++) { acc[r][0]=acc[r][1]=acc[r][2]=acc[r][3]=0.f; }

    for (int kc = 0; kc < C; kc += 16) {
        __syncthreads();
        for (int i = t; i < 16 * 32; i += 256) {
            int r = i >> 5, c4 = i & 31;
            reinterpret_cast<float4*>(&Ws[r][0])[c4] =
                reinterpret_cast<const float4*>(W)[(size_t)(kc + r) * 32 + c4];
        }
        __syncthreads();
        #pragma unroll
        for (int kk = 0; kk < 16; kk++) {
            float4 w = reinterpret_cast<float4*>(&Ws[kk][0])[tx];
            #pragma unroll
            for (int r = 0; r < 8; r++) {
                float a = As[ty * 8 + r][kc + kk];   // warp-broadcast
                acc[r][0] += a * w.x;
                acc[r][1] += a * w.y;
                acc[r][2] += a * w.z;
                acc[r][3] += a * w.w;
            }
        }
    }

    #pragma unroll
    for (int r = 0; r < 8; r++) {
        int gr = row0 + ty * 8 + r;
        if (gr < nrows) {
            float s = dinv[gr];
            float4 h, g;
            h.x = acc[r][0] * s;  h.y = acc[r][1] * s;
            h.z = acc[r][2] * s;  h.w = acc[r][3] * s;
            g.x = h.x * s;  g.y = h.y * s;  g.z = h.z * s;  g.w = h.w * s;
            reinterpret_cast<float4*>(hs )[(size_t)gr * 32 + tx] = h;
            reinterpret_cast<float4*>(agg)[(size_t)gr * 32 + tx] = g;
        }
    }
}

// ---------------------------------------------------------------------------
// Edge scatter: one warp per edge.
//   agg[col] += hs[row] * dinv[col]     (hs already carries dinv[row])
// Vector atomic red.global.add.v4.f32 (sm_90+): 4 floats per lane, 1 op.
// ---------------------------------------------------------------------------
__global__ __launch_bounds__(256) void scatter_kernel(
    const int* __restrict__ ei, const float* __restrict__ hs,
    float* __restrict__ agg, const float* __restrict__ dinv, int e, int n)
{
    int warp = (blockIdx.x * blockDim.x + threadIdx.x) >> 5;
    int lane = threadIdx.x & 31;
    if (warp >= e) return;
    int r = ei[warp];        // source
    int c = ei[e + warp];    // target
    if ((unsigned)r >= (unsigned)n || (unsigned)c >= (unsigned)n) return;
    float s = dinv[c];
    float4 v = reinterpret_cast<const float4*>(hs)[(size_t)r * 32 + lane];
    float* p = agg + (size_t)c * C + lane * 4;
    asm volatile("red.global.add.v4.f32 [%0], {%1,%2,%3,%4};"
                 :: "l"(p), "f"(v.x * s), "f"(v.y * s), "f"(v.z * s), "f"(v.w * s)
                 : "memory");
}

// ---------------------------------------------------------------------------
// out[i] = relu(agg[i] + b[i % 128])
// ---------------------------------------------------------------------------
__global__ __launch_bounds__(256) void bias_relu_kernel(
    const float* __restrict__ agg, const float* __restrict__ b,
    float* __restrict__ out, size_t total)
{
    size_t i = (size_t)blockIdx.x * blockDim.x + threadIdx.x;
    if (i < total) {
        float v = agg[i] + b[i & (C - 1)];
        out[i] = v > 0.f ? v : 0.f;
    }
}

// ---------------------------------------------------------------------------
// Final: per node (one warp): v = agg + b2; L2-normalize; emb out;
// logits = emb @ Wd + bd; log_softmax; logits out.
// Block = 256 threads = 8 warps = 8 nodes. Wd staged to smem (32 KB).
// ---------------------------------------------------------------------------
__global__ __launch_bounds__(256) void final_kernel(
    const float* __restrict__ agg, const float* __restrict__ b2,
    const float* __restrict__ Wd, const float* __restrict__ bd,
    float* __restrict__ out_logits, float* __restrict__ out_emb, int n)
{
    __shared__ float Wds[C * OC];     // 32 KB, [k][c] layout
    __shared__ float embS[8][C];      //  4 KB
    int t = threadIdx.x;
    for (int i = t; i < C * OC / 4; i += 256)
        reinterpret_cast<float4*>(Wds)[i] = reinterpret_cast<const float4*>(Wd)[i];
    __syncthreads();

    int lane = t & 31;
    int w    = t >> 5;
    int node = blockIdx.x * 8 + w;
    if (node >= n) return;

    float4 v  = reinterpret_cast<const float4*>(agg)[(size_t)node * 32 + lane];
    float4 bb = reinterpret_cast<const float4*>(b2)[lane];
    v.x += bb.x; v.y += bb.y; v.z += bb.z; v.w += bb.w;

    float ss = v.x * v.x + v.y * v.y + v.z * v.z + v.w * v.w;
    #pragma unroll
    for (int o = 16; o; o >>= 1) ss += __shfl_xor_sync(0xffffffffu, ss, o);
    float inv = 1.0f / (sqrtf(ss) + 1e-12f);

    float4 e;
    e.x = v.x * inv; e.y = v.y * inv; e.z = v.z * inv; e.w = v.w * inv;
    if (out_emb)
        reinterpret_cast<float4*>(out_emb)[(size_t)node * 32 + lane] = e;
    reinterpret_cast<float4*>(&embS[w][0])[lane] = e;
    __syncwarp();

    // logits: lane covers cols {lane, lane+32}
    float l0 = bd[lane], l1 = bd[lane + 32];
    #pragma unroll
    for (int k = 0; k < C; k++) {
        float ek = embS[w][k];                 // warp-broadcast
        l0 += ek * Wds[k * OC + lane];
        l1 += ek * Wds[k * OC + lane + 32];
    }

    float m = fmaxf(l0, l1);
    #pragma unroll
    for (int o = 16; o; o >>= 1) m = fmaxf(m, __shfl_xor_sync(0xffffffffu, m, o));
    float s = expf(l0 - m) + expf(l1 - m);
    #pragma unroll
    for (int o = 16; o; o >>= 1) s += __shfl_xor_sync(0xffffffffu, s, o);
    float lse = m + logf(s);

    if (out_logits) {
        out_logits[(size_t)node * OC + lane]      = l0 - lse;
        out_logits[(size_t)node * OC + lane + 32] = l1 - lse;
    }
}

// ---------------------------------------------------------------------------
// launch
// ---------------------------------------------------------------------------
extern "C" void kernel_launch(void* const* d_in, const int* in_sizes, int n_in,
                              void* d_out, int out_size)
{
    const float* x  = (const float*)d_in[0];
    const int*   ei = (const int*)d_in[1];    // int32! (JAX x64 disabled)
    const float* W1 = (const float*)d_in[2];
    const float* b1 = (const float*)d_in[3];
    const float* W2 = (const float*)d_in[4];
    const float* b2 = (const float*)d_in[5];
    const float* Wd = (const float*)d_in[6];
    const float* bd = (const float*)d_in[7];

    int n = in_sizes[0] / C;       // 100000
    int e = in_sizes[1] / 2;       // 1600000

    float* out = (float*)d_out;
    float* out_logits = out;
    float* out_emb    = nullptr;
    if ((size_t)out_size >= (size_t)n * (OC + C)) {
        out_emb = out + (size_t)n * OC;
    } else if (out_size == n * C) {          // embeddings-only layout
        out_logits = nullptr;
        out_emb    = out;
    }

    float *deg, *dinv, *bufH, *bufG, *bufX;
    cudaGetSymbolAddress((void**)&deg,  g_deg);
    cudaGetSymbolAddress((void**)&dinv, g_dinv);
    cudaGetSymbolAddress((void**)&bufH, g_bufH);
    cudaGetSymbolAddress((void**)&bufG, g_bufG);
    cudaGetSymbolAddress((void**)&bufX, g_bufX);

    // normalization
    deg_init_kernel<<<(n + 255) / 256, 256>>>(deg, n);
    deg_accum_kernel<<<(e + 255) / 256, 256>>>(ei, deg, e, n);
    dinv_kernel<<<(n + 255) / 256, 256>>>(deg, dinv, n);

    int gemm_blocks    = (n + 63) / 64;
    int scatter_blocks = (int)(((long long)e * 32 + 255) / 256);
    size_t total       = (size_t)n * C;
    int ew_blocks      = (int)((total + 255) / 256);

    // layer 1
    gemm_scaled_kernel<<<gemm_blocks, 256>>>(x, W1, dinv, bufH, bufG, n);
    scatter_kernel<<<scatter_blocks, 256>>>(ei, bufH, bufG, dinv, e, n);
    bias_relu_kernel<<<ew_blocks, 256>>>(bufG, b1, bufX, total);

    // layer 2
    gemm_scaled_kernel<<<gemm_blocks, 256>>>(bufX, W2, dinv, bufH, bufG, n);
    scatter_kernel<<<scatter_blocks, 256>>>(ei, bufH, bufG, dinv, e, n);

    // normalize + decode + log_softmax
    final_kernel<<<(n + 7) / 8, 256>>>(bufG, b2, Wd, bd, out_logits, out_emb, n);
}

// round 6
// speedup vs baseline: 1.4138x; 1.4138x over previous
#include <cuda_runtime.h>
#include <cuda_bf16.h>

// Problem constants
#define NN 100000
#define EE 1600000
#define C  128      // IN_C = H1 = H2 = 128
#define OC 64

// Scratch (allocation-free rule: __device__ globals)
__device__ int   g_cnt[NN];          // in-degree histogram (no self-loop)
__device__ int   g_cursor[NN];       // bucket-fill cursors
__device__ int   g_rowptr[NN + 1];   // CSR row pointers (by target col)
__device__ int   g_csrsrc[EE];       // CSR source indices
__device__ float g_dinv[NN];
__device__ float g_bufH[(size_t)NN * C];   // hs = (A*W)*dinv[row]
__device__ float g_bufG[(size_t)NN * C];   // layer-2 aggregate (+b2)
__device__ float g_bufX[(size_t)NN * C];   // relu(layer1) output

// ---------------------------------------------------------------------------
// CSR build:  zero -> histogram -> dinv -> scan -> fill
// edge_index is int32 (JAX x64 disabled): ei[0..e) = row, ei[e..2e) = col.
// ---------------------------------------------------------------------------
__global__ void zero_kernel(int* __restrict__ cnt, int* __restrict__ cursor, int n) {
    int i = blockIdx.x * blockDim.x + threadIdx.x;
    if (i < n) { cnt[i] = 0; cursor[i] = 0; }
}

__global__ void hist_kernel(const int* __restrict__ ei,
                            int* __restrict__ cnt, int e, int n) {
    int i = blockIdx.x * blockDim.x + threadIdx.x;
    if (i < e) {
        int c = ei[e + i];
        if ((unsigned)c < (unsigned)n) atomicAdd(&cnt[c], 1);
    }
}

__global__ void dinv_kernel(const int* __restrict__ cnt,
                            float* __restrict__ dinv, int n) {
    int i = blockIdx.x * blockDim.x + threadIdx.x;
    if (i < n) dinv[i] = rsqrtf((float)cnt[i] + 1.0f);   // +1 self-loop
}

// Single-block exclusive scan over n counts -> rowptr[0..n]
#define SCAN_T 1024
__global__ __launch_bounds__(SCAN_T) void scan_kernel(
    const int* __restrict__ cnt, int* __restrict__ rowptr, int n)
{
    __shared__ int warpsum[32];
    int t    = threadIdx.x;
    int lane = t & 31;
    int wid  = t >> 5;
    int chunk = (n + SCAN_T - 1) / SCAN_T;
    int lo = t * chunk;
    int hi = min(lo + chunk, n);

    int sum = 0;
    for (int i = lo; i < hi; i++) sum += cnt[i];

    // warp inclusive scan of per-thread sums
    int v = sum;
    #pragma unroll
    for (int o = 1; o < 32; o <<= 1) {
        int x = __shfl_up_sync(0xffffffffu, v, o);
        if (lane >= o) v += x;
    }
    if (lane == 31) warpsum[wid] = v;
    __syncthreads();
    if (wid == 0) {
        int w = warpsum[lane];
        #pragma unroll
        for (int o = 1; o < 32; o <<= 1) {
            int x = __shfl_up_sync(0xffffffffu, w, o);
            if (lane >= o) w += x;
        }
        warpsum[lane] = w;
    }
    __syncthreads();
    int base = (wid > 0) ? warpsum[wid - 1] : 0;
    int excl = v + base - sum;          // exclusive prefix for this thread's chunk

    int run = excl;
    for (int i = lo; i < hi; i++) { rowptr[i] = run; run += cnt[i]; }
    if (t == SCAN_T - 1) rowptr[n] = v + base;   // total = last inclusive
}

__global__ void fill_kernel(const int* __restrict__ ei,
                            const int* __restrict__ rowptr,
                            int* __restrict__ cursor,
                            int* __restrict__ csrsrc, int e, int n)
{
    int i = blockIdx.x * blockDim.x + threadIdx.x;
    if (i < e) {
        int r = ei[i];
        int c = ei[e + i];
        if ((unsigned)r < (unsigned)n && (unsigned)c < (unsigned)n) {
            int pos = atomicAdd(&cursor[c], 1);
            csrsrc[rowptr[c] + pos] = r;
        }
    }
}

// ---------------------------------------------------------------------------
// GEMM: [n x 128] @ [128 x 128], epilogue writes hs[row] = acc * dinv[row].
// Block: 256 threads, tile 64 rows x 128 cols; thread -> 8 rows x 4 cols.
// ---------------------------------------------------------------------------
__global__ __launch_bounds__(256) void gemm_scaled_kernel(
    const float* __restrict__ A, const float* __restrict__ W,
    const float* __restrict__ dinv, float* __restrict__ hs, int nrows)
{
    __shared__ float As[64][C];    // 32 KB
    __shared__ float Ws[16][C];    //  8 KB
    int t  = threadIdx.x;
    int tx = t & 31;
    int ty = t >> 5;
    int row0 = blockIdx.x * 64;

    for (int i = t; i < 64 * 32; i += 256) {
        int r = i >> 5, c4 = i & 31;
        int gr = row0 + r;
        float4 v = (gr < nrows)
                     ? reinterpret_cast<const float4*>(A)[(size_t)gr * 32 + c4]
                     : make_float4(0.f, 0.f, 0.f, 0.f);
        reinterpret_cast<float4*>(&As[r][0])[c4] = v;
    }

    float acc[8][4];
    #pragma unroll
    for (int r = 0; r < 8; r++) { acc[r][0]=acc[r][1]=acc[r][2]=acc[r][3]=0.f; }

    for (int kc = 0; kc < C; kc += 16) {
        __syncthreads();
        for (int i = t; i < 16 * 32; i += 256) {
            int r = i >> 5, c4 = i & 31;
            reinterpret_cast<float4*>(&Ws[r][0])[c4] =
                reinterpret_cast<const float4*>(W)[(size_t)(kc + r) * 32 + c4];
        }
        __syncthreads();
        #pragma unroll
        for (int kk = 0; kk < 16; kk++) {
            float4 w = reinterpret_cast<float4*>(&Ws[kk][0])[tx];
            #pragma unroll
            for (int r = 0; r < 8; r++) {
                float a = As[ty * 8 + r][kc + kk];
                acc[r][0] += a * w.x;
                acc[r][1] += a * w.y;
                acc[r][2] += a * w.z;
                acc[r][3] += a * w.w;
            }
        }
    }

    #pragma unroll
    for (int r = 0; r < 8; r++) {
        int gr = row0 + ty * 8 + r;
        if (gr < nrows) {
            float s = dinv[gr];
            float4 h;
            h.x = acc[r][0] * s;  h.y = acc[r][1] * s;
            h.z = acc[r][2] * s;  h.w = acc[r][3] * s;
            reinterpret_cast<float4*>(hs)[(size_t)gr * 32 + tx] = h;
        }
    }
}

// ---------------------------------------------------------------------------
// Gather aggregation: one warp per node.
//   out[node] = act( (hs[node] + sum_j hs[src_j]) * dinv[node] + bias )
// hs already carries dinv[row]; self term hs[node]*dinv[node] = h*dinv^2.
// ---------------------------------------------------------------------------
template<bool RELU>
__global__ __launch_bounds__(256) void gather_kernel(
    const int* __restrict__ rowptr, const int* __restrict__ csrsrc,
    const float* __restrict__ hs, const float* __restrict__ dinv,
    const float* __restrict__ bias, float* __restrict__ out, int n)
{
    int w    = (blockIdx.x * blockDim.x + threadIdx.x) >> 5;
    int lane = threadIdx.x & 31;
    if (w >= n) return;

    const float4* H = reinterpret_cast<const float4*>(hs);
    int start = rowptr[w];
    int end   = rowptr[w + 1];

    float4 acc = H[(size_t)w * 32 + lane];    // self contribution
    int j = start;
    for (; j + 4 <= end; j += 4) {
        int r0 = csrsrc[j], r1 = csrsrc[j+1], r2 = csrsrc[j+2], r3 = csrsrc[j+3];
        float4 v0 = H[(size_t)r0 * 32 + lane];
        float4 v1 = H[(size_t)r1 * 32 + lane];
        float4 v2 = H[(size_t)r2 * 32 + lane];
        float4 v3 = H[(size_t)r3 * 32 + lane];
        float4 a, b;
        a.x = v0.x + v1.x; a.y = v0.y + v1.y; a.z = v0.z + v1.z; a.w = v0.w + v1.w;
        b.x = v2.x + v3.x; b.y = v2.y + v3.y; b.z = v2.z + v3.z; b.w = v2.w + v3.w;
        acc.x += a.x + b.x; acc.y += a.y + b.y;
        acc.z += a.z + b.z; acc.w += a.w + b.w;
    }
    for (; j < end; j++) {
        int r = csrsrc[j];
        float4 v = H[(size_t)r * 32 + lane];
        acc.x += v.x; acc.y += v.y; acc.z += v.z; acc.w += v.w;
    }

    float s  = dinv[w];
    float4 bb = reinterpret_cast<const float4*>(bias)[lane];
    acc.x = fmaf(acc.x, s, bb.x);
    acc.y = fmaf(acc.y, s, bb.y);
    acc.z = fmaf(acc.z, s, bb.z);
    acc.w = fmaf(acc.w, s, bb.w);
    if (RELU) {
        acc.x = fmaxf(acc.x, 0.f); acc.y = fmaxf(acc.y, 0.f);
        acc.z = fmaxf(acc.z, 0.f); acc.w = fmaxf(acc.w, 0.f);
    }
    reinterpret_cast<float4*>(out)[(size_t)w * 32 + lane] = acc;
}

// ---------------------------------------------------------------------------
// Final: per node (one warp): v = agg (b2 already applied); L2-normalize;
// emb out; logits = emb @ Wd + bd; log_softmax; logits out.
// Block = 256 threads = 8 warps = 8 nodes. Wd staged to smem (32 KB).
// ---------------------------------------------------------------------------
__global__ __launch_bounds__(256) void final_kernel(
    const float* __restrict__ agg,
    const float* __restrict__ Wd, const float* __restrict__ bd,
    float* __restrict__ out_logits, float* __restrict__ out_emb, int n)
{
    __shared__ float Wds[C * OC];     // 32 KB, [k][c] layout
    __shared__ float embS[8][C];      //  4 KB
    int t = threadIdx.x;
    for (int i = t; i < C * OC / 4; i += 256)
        reinterpret_cast<float4*>(Wds)[i] = reinterpret_cast<const float4*>(Wd)[i];
    __syncthreads();

    int lane = t & 31;
    int w    = t >> 5;
    int node = blockIdx.x * 8 + w;
    if (node >= n) return;

    float4 v = reinterpret_cast<const float4*>(agg)[(size_t)node * 32 + lane];

    float ss = v.x * v.x + v.y * v.y + v.z * v.z + v.w * v.w;
    #pragma unroll
    for (int o = 16; o; o >>= 1) ss += __shfl_xor_sync(0xffffffffu, ss, o);
    float inv = 1.0f / (sqrtf(ss) + 1e-12f);

    float4 e;
    e.x = v.x * inv; e.y = v.y * inv; e.z = v.z * inv; e.w = v.w * inv;
    if (out_emb)
        reinterpret_cast<float4*>(out_emb)[(size_t)node * 32 + lane] = e;
    reinterpret_cast<float4*>(&embS[w][0])[lane] = e;
    __syncwarp();

    float l0 = bd[lane], l1 = bd[lane + 32];
    #pragma unroll
    for (int k = 0; k < C; k++) {
        float ek = embS[w][k];
        l0 += ek * Wds[k * OC + lane];
        l1 += ek * Wds[k * OC + lane + 32];
    }

    float m = fmaxf(l0, l1);
    #pragma unroll
    for (int o = 16; o; o >>= 1) m = fmaxf(m, __shfl_xor_sync(0xffffffffu, m, o));
    float s = expf(l0 - m) + expf(l1 - m);
    #pragma unroll
    for (int o = 16; o; o >>= 1) s += __shfl_xor_sync(0xffffffffu, s, o);
    float lse = m + logf(s);

    if (out_logits) {
        out_logits[(size_t)node * OC + lane]      = l0 - lse;
        out_logits[(size_t)node * OC + lane + 32] = l1 - lse;
    }
}

// ---------------------------------------------------------------------------
// launch
// ---------------------------------------------------------------------------
extern "C" void kernel_launch(void* const* d_in, const int* in_sizes, int n_in,
                              void* d_out, int out_size)
{
    const float* x  = (const float*)d_in[0];
    const int*   ei = (const int*)d_in[1];    // int32 (JAX x64 disabled)
    const float* W1 = (const float*)d_in[2];
    const float* b1 = (const float*)d_in[3];
    const float* W2 = (const float*)d_in[4];
    const float* b2 = (const float*)d_in[5];
    const float* Wd = (const float*)d_in[6];
    const float* bd = (const float*)d_in[7];

    int n = in_sizes[0] / C;       // 100000
    int e = in_sizes[1] / 2;       // 1600000

    float* out = (float*)d_out;
    float* out_logits = out;
    float* out_emb    = nullptr;
    if ((size_t)out_size >= (size_t)n * (OC + C)) {
        out_emb = out + (size_t)n * OC;
    } else if (out_size == n * C) {
        out_logits = nullptr;
        out_emb    = out;
    }

    int *cnt, *cursor, *rowptr, *csrsrc;
    float *dinv, *bufH, *bufG, *bufX;
    cudaGetSymbolAddress((void**)&cnt,    g_cnt);
    cudaGetSymbolAddress((void**)&cursor, g_cursor);
    cudaGetSymbolAddress((void**)&rowptr, g_rowptr);
    cudaGetSymbolAddress((void**)&csrsrc, g_csrsrc);
    cudaGetSymbolAddress((void**)&dinv,   g_dinv);
    cudaGetSymbolAddress((void**)&bufH,   g_bufH);
    cudaGetSymbolAddress((void**)&bufG,   g_bufG);
    cudaGetSymbolAddress((void**)&bufX,   g_bufX);

    int nb = (n + 255) / 256;
    int eb = (e + 255) / 256;

    // CSR build (shared by both layers)
    zero_kernel<<<nb, 256>>>(cnt, cursor, n);
    hist_kernel<<<eb, 256>>>(ei, cnt, e, n);
    dinv_kernel<<<nb, 256>>>(cnt, dinv, n);
    scan_kernel<<<1, SCAN_T>>>(cnt, rowptr, n);
    fill_kernel<<<eb, 256>>>(ei, rowptr, cursor, csrsrc, e, n);

    int gemm_blocks   = (n + 63) / 64;
    int gather_blocks = (int)(((long long)n * 32 + 255) / 256);

    // layer 1
    gemm_scaled_kernel<<<gemm_blocks, 256>>>(x, W1, dinv, bufH, n);
    gather_kernel<true><<<gather_blocks, 256>>>(rowptr, csrsrc, bufH, dinv, b1, bufX, n);

    // layer 2
    gemm_scaled_kernel<<<gemm_blocks, 256>>>(bufX, W2, dinv, bufH, n);
    gather_kernel<false><<<gather_blocks, 256>>>(rowptr, csrsrc, bufH, dinv, b2, bufG, n);

    // normalize + decode + log_softmax
    final_kernel<<<(n + 7) / 8, 256>>>(bufG, Wd, bd, out_logits, out_emb, n);
}

// round 7
// speedup vs baseline: 1.6095x; 1.1384x over previous
#include <cuda_runtime.h>
#include <cuda_bf16.h>

// Problem constants
#define NN 100000
#define EE 1600000
#define C  128      // IN_C = H1 = H2 = 128
#define OC 64

#define TILE 1024                       // counts per scan block
#define MAXB ((NN + TILE - 1) / TILE)   // 98

// Scratch (allocation-free rule: __device__ globals)
__device__ int   g_cnt[NN];          // in-degree histogram (no self-loop)
__device__ int   g_cursor[NN];       // bucket-fill cursors
__device__ int   g_rowptr[NN + 1];   // CSR row pointers (by target col)
__device__ int   g_blocksum[MAXB + 1];
__device__ int   g_csrsrc[EE];       // CSR source indices
__device__ float g_dinv[NN];
__device__ float g_bufH[(size_t)NN * C];   // hs = (A*W)*dinv[row]
__device__ float g_bufG[(size_t)NN * C];   // layer-2 aggregate (+b2)
__device__ float g_bufX[(size_t)NN * C];   // relu(layer1) output

// ---------------------------------------------------------------------------
// CSR build:  zero -> histogram -> dinv -> 3-phase scan -> fill
// edge_index is int32 (JAX x64 disabled): ei[0..e) = row, ei[e..2e) = col.
// ---------------------------------------------------------------------------
__global__ void zero_kernel(int* __restrict__ cnt, int* __restrict__ cursor, int n) {
    int i = blockIdx.x * blockDim.x + threadIdx.x;
    if (i < n) { cnt[i] = 0; cursor[i] = 0; }
}

__global__ void hist_kernel(const int* __restrict__ ei,
                            int* __restrict__ cnt, int e, int n) {
    int i = blockIdx.x * blockDim.x + threadIdx.x;
    if (i < e) {
        int c = ei[e + i];
        if ((unsigned)c < (unsigned)n) atomicAdd(&cnt[c], 1);
    }
}

__global__ void dinv_kernel(const int* __restrict__ cnt,
                            float* __restrict__ dinv, int n) {
    int i = blockIdx.x * blockDim.x + threadIdx.x;
    if (i < n) dinv[i] = rsqrtf((float)cnt[i] + 1.0f);   // +1 self-loop
}

// Phase 1: per-block (1024-count tile) sums
__global__ __launch_bounds__(256) void partial_kernel(
    const int* __restrict__ cnt, int* __restrict__ blocksum, int n)
{
    int t = threadIdx.x;
    int base = blockIdx.x * TILE + t * 4;
    int s = 0;
    #pragma unroll
    for (int k = 0; k < 4; k++)
        if (base + k < n) s += cnt[base + k];

    // block reduce
    #pragma unroll
    for (int o = 16; o; o >>= 1) s += __shfl_xor_sync(0xffffffffu, s, o);
    __shared__ int ws[8];
    if ((t & 31) == 0) ws[t >> 5] = s;
    __syncthreads();
    if (t == 0) {
        int tot = 0;
        #pragma unroll
        for (int w = 0; w < 8; w++) tot += ws[w];
        blocksum[blockIdx.x] = tot;
    }
}

// Phase 2: exclusive scan of block sums (nb <= 128); writes rowptr[n] = total
__global__ __launch_bounds__(128) void scan_sums_kernel(
    int* __restrict__ blocksum, int* __restrict__ rowptr, int nb, int n)
{
    int t = threadIdx.x;
    int lane = t & 31;
    int wid  = t >> 5;
    int v = (t < nb) ? blocksum[t] : 0;
    int incl = v;
    #pragma unroll
    for (int o = 1; o < 32; o <<= 1) {
        int x = __shfl_up_sync(0xffffffffu, incl, o);
        if (lane >= o) incl += x;
    }
    __shared__ int ws[4];
    if (lane == 31) ws[wid] = incl;
    __syncthreads();
    int base = 0;
    #pragma unroll
    for (int w = 0; w < 4; w++) base += (w < wid) ? ws[w] : 0;
    if (t < nb) blocksum[t] = base + incl - v;       // exclusive
    if (t == nb - 1) rowptr[n] = base + incl;        // total
}

// Phase 3: local scan per tile + block offset -> rowptr
__global__ __launch_bounds__(256) void write_rowptr_kernel(
    const int* __restrict__ cnt, const int* __restrict__ blocksum,
    int* __restrict__ rowptr, int n)
{
    int t = threadIdx.x;
    int lane = t & 31;
    int wid  = t >> 5;
    int base = blockIdx.x * TILE + t * 4;

    int c[4];
    #pragma unroll
    for (int k = 0; k < 4; k++)
        c[k] = (base + k < n) ? cnt[base + k] : 0;
    int s = c[0] + c[1] + c[2] + c[3];

    int incl = s;
    #pragma unroll
    for (int o = 1; o < 32; o <<= 1) {
        int x = __shfl_up_sync(0xffffffffu, incl, o);
        if (lane >= o) incl += x;
    }
    __shared__ int ws[8];
    if (lane == 31) ws[wid] = incl;
    __syncthreads();
    int wbase = 0;
    #pragma unroll
    for (int w = 0; w < 8; w++) wbase += (w < wid) ? ws[w] : 0;

    int run = blocksum[blockIdx.x] + wbase + incl - s;   // exclusive prefix
    #pragma unroll
    for (int k = 0; k < 4; k++) {
        if (base + k < n) rowptr[base + k] = run;
        run += c[k];
    }
}

__global__ void fill_kernel(const int* __restrict__ ei,
                            const int* __restrict__ rowptr,
                            int* __restrict__ cursor,
                            int* __restrict__ csrsrc, int e, int n)
{
    int i = blockIdx.x * blockDim.x + threadIdx.x;
    if (i < e) {
        int r = ei[i];
        int c = ei[e + i];
        if ((unsigned)r < (unsigned)n && (unsigned)c < (unsigned)n) {
            int pos = atomicAdd(&cursor[c], 1);
            csrsrc[rowptr[c] + pos] = r;
        }
    }
}

// ---------------------------------------------------------------------------
// GEMM: [n x 128] @ [128 x 128], epilogue writes hs[row] = acc * dinv[row].
// Block: 256 threads, tile 64 rows x 128 cols; thread -> 8 rows x 4 cols.
// ---------------------------------------------------------------------------
__global__ __launch_bounds__(256) void gemm_scaled_kernel(
    const float* __restrict__ A, const float* __restrict__ W,
    const float* __restrict__ dinv, float* __restrict__ hs, int nrows)
{
    __shared__ float As[64][C];    // 32 KB
    __shared__ float Ws[16][C];    //  8 KB
    int t  = threadIdx.x;
    int tx = t & 31;
    int ty = t >> 5;
    int row0 = blockIdx.x * 64;

    for (int i = t; i < 64 * 32; i += 256) {
        int r = i >> 5, c4 = i & 31;
        int gr = row0 + r;
        float4 v = (gr < nrows)
                     ? reinterpret_cast<const float4*>(A)[(size_t)gr * 32 + c4]
                     : make_float4(0.f, 0.f, 0.f, 0.f);
        reinterpret_cast<float4*>(&As[r][0])[c4] = v;
    }

    float acc[8][4];
    #pragma unroll
    for (int r = 0; r < 8; r++) { acc[r][0]=acc[r][1]=acc[r][2]=acc[r][3]=0.f; }

    for (int kc = 0; kc < C; kc += 16) {
        __syncthreads();
        for (int i = t; i < 16 * 32; i += 256) {
            int r = i >> 5, c4 = i & 31;
            reinterpret_cast<float4*>(&Ws[r][0])[c4] =
                reinterpret_cast<const float4*>(W)[(size_t)(kc + r) * 32 + c4];
        }
        __syncthreads();
        #pragma unroll
        for (int kk = 0; kk < 16; kk++) {
            float4 w = reinterpret_cast<float4*>(&Ws[kk][0])[tx];
            #pragma unroll
            for (int r = 0; r < 8; r++) {
                float a = As[ty * 8 + r][kc + kk];
                acc[r][0] += a * w.x;
                acc[r][1] += a * w.y;
                acc[r][2] += a * w.z;
                acc[r][3] += a * w.w;
            }
        }
    }

    #pragma unroll
    for (int r = 0; r < 8; r++) {
        int gr = row0 + ty * 8 + r;
        if (gr < nrows) {
            float s = dinv[gr];
            float4 h;
            h.x = acc[r][0] * s;  h.y = acc[r][1] * s;
            h.z = acc[r][2] * s;  h.w = acc[r][3] * s;
            reinterpret_cast<float4*>(hs)[(size_t)gr * 32 + tx] = h;
        }
    }
}

// ---------------------------------------------------------------------------
// Gather aggregation: one warp per node.
//   out[node] = act( (hs[node] + sum_j hs[src_j]) * dinv[node] + bias )
// ---------------------------------------------------------------------------
template<bool RELU>
__global__ __launch_bounds__(256) void gather_kernel(
    const int* __restrict__ rowptr, const int* __restrict__ csrsrc,
    const float* __restrict__ hs, const float* __restrict__ dinv,
    const float* __restrict__ bias, float* __restrict__ out, int n)
{
    int w    = (blockIdx.x * blockDim.x + threadIdx.x) >> 5;
    int lane = threadIdx.x & 31;
    if (w >= n) return;

    const float4* H = reinterpret_cast<const float4*>(hs);
    int start = rowptr[w];
    int end   = rowptr[w + 1];

    float4 acc = H[(size_t)w * 32 + lane];    // self contribution
    int j = start;
    for (; j + 4 <= end; j += 4) {
        int r0 = csrsrc[j], r1 = csrsrc[j+1], r2 = csrsrc[j+2], r3 = csrsrc[j+3];
        float4 v0 = H[(size_t)r0 * 32 + lane];
        float4 v1 = H[(size_t)r1 * 32 + lane];
        float4 v2 = H[(size_t)r2 * 32 + lane];
        float4 v3 = H[(size_t)r3 * 32 + lane];
        float4 a, b;
        a.x = v0.x + v1.x; a.y = v0.y + v1.y; a.z = v0.z + v1.z; a.w = v0.w + v1.w;
        b.x = v2.x + v3.x; b.y = v2.y + v3.y; b.z = v2.z + v3.z; b.w = v2.w + v3.w;
        acc.x += a.x + b.x; acc.y += a.y + b.y;
        acc.z += a.z + b.z; acc.w += a.w + b.w;
    }
    for (; j < end; j++) {
        int r = csrsrc[j];
        float4 v = H[(size_t)r * 32 + lane];
        acc.x += v.x; acc.y += v.y; acc.z += v.z; acc.w += v.w;
    }

    float s  = dinv[w];
    float4 bb = reinterpret_cast<const float4*>(bias)[lane];
    acc.x = fmaf(acc.x, s, bb.x);
    acc.y = fmaf(acc.y, s, bb.y);
    acc.z = fmaf(acc.z, s, bb.z);
    acc.w = fmaf(acc.w, s, bb.w);
    if (RELU) {
        acc.x = fmaxf(acc.x, 0.f); acc.y = fmaxf(acc.y, 0.f);
        acc.z = fmaxf(acc.z, 0.f); acc.w = fmaxf(acc.w, 0.f);
    }
    reinterpret_cast<float4*>(out)[(size_t)w * 32 + lane] = acc;
}

// ---------------------------------------------------------------------------
// Final: per node (one warp): v = agg (b2 already applied); L2-normalize;
// emb out; logits = emb @ Wd + bd; log_softmax; logits out.
// ---------------------------------------------------------------------------
__global__ __launch_bounds__(256) void final_kernel(
    const float* __restrict__ agg,
    const float* __restrict__ Wd, const float* __restrict__ bd,
    float* __restrict__ out_logits, float* __restrict__ out_emb, int n)
{
    __shared__ float Wds[C * OC];     // 32 KB, [k][c] layout
    __shared__ float embS[8][C];      //  4 KB
    int t = threadIdx.x;
    for (int i = t; i < C * OC / 4; i += 256)
        reinterpret_cast<float4*>(Wds)[i] = reinterpret_cast<const float4*>(Wd)[i];
    __syncthreads();

    int lane = t & 31;
    int w    = t >> 5;
    int node = blockIdx.x * 8 + w;
    if (node >= n) return;

    float4 v = reinterpret_cast<const float4*>(agg)[(size_t)node * 32 + lane];

    float ss = v.x * v.x + v.y * v.y + v.z * v.z + v.w * v.w;
    #pragma unroll
    for (int o = 16; o; o >>= 1) ss += __shfl_xor_sync(0xffffffffu, ss, o);
    float inv = 1.0f / (sqrtf(ss) + 1e-12f);

    float4 e;
    e.x = v.x * inv; e.y = v.y * inv; e.z = v.z * inv; e.w = v.w * inv;
    if (out_emb)
        reinterpret_cast<float4*>(out_emb)[(size_t)node * 32 + lane] = e;
    reinterpret_cast<float4*>(&embS[w][0])[lane] = e;
    __syncwarp();

    float l0 = bd[lane], l1 = bd[lane + 32];
    #pragma unroll
    for (int k = 0; k < C; k++) {
        float ek = embS[w][k];
        l0 += ek * Wds[k * OC + lane];
        l1 += ek * Wds[k * OC + lane + 32];
    }

    float m = fmaxf(l0, l1);
    #pragma unroll
    for (int o = 16; o; o >>= 1) m = fmaxf(m, __shfl_xor_sync(0xffffffffu, m, o));
    float s = expf(l0 - m) + expf(l1 - m);
    #pragma unroll
    for (int o = 16; o; o >>= 1) s += __shfl_xor_sync(0xffffffffu, s, o);
    float lse = m + logf(s);

    if (out_logits) {
        out_logits[(size_t)node * OC + lane]      = l0 - lse;
        out_logits[(size_t)node * OC + lane + 32] = l1 - lse;
    }
}

// ---------------------------------------------------------------------------
// launch
// ---------------------------------------------------------------------------
extern "C" void kernel_launch(void* const* d_in, const int* in_sizes, int n_in,
                              void* d_out, int out_size)
{
    const float* x  = (const float*)d_in[0];
    const int*   ei = (const int*)d_in[1];    // int32 (JAX x64 disabled)
    const float* W1 = (const float*)d_in[2];
    const float* b1 = (const float*)d_in[3];
    const float* W2 = (const float*)d_in[4];
    const float* b2 = (const float*)d_in[5];
    const float* Wd = (const float*)d_in[6];
    const float* bd = (const float*)d_in[7];

    int n = in_sizes[0] / C;       // 100000
    int e = in_sizes[1] / 2;       // 1600000

    float* out = (float*)d_out;
    float* out_logits = out;
    float* out_emb    = nullptr;
    if ((size_t)out_size >= (size_t)n * (OC + C)) {
        out_emb = out + (size_t)n * OC;
    } else if (out_size == n * C) {
        out_logits = nullptr;
        out_emb    = out;
    }

    int *cnt, *cursor, *rowptr, *csrsrc, *blocksum;
    float *dinv, *bufH, *bufG, *bufX;
    cudaGetSymbolAddress((void**)&cnt,      g_cnt);
    cudaGetSymbolAddress((void**)&cursor,   g_cursor);
    cudaGetSymbolAddress((void**)&rowptr,   g_rowptr);
    cudaGetSymbolAddress((void**)&csrsrc,   g_csrsrc);
    cudaGetSymbolAddress((void**)&blocksum, g_blocksum);
    cudaGetSymbolAddress((void**)&dinv,     g_dinv);
    cudaGetSymbolAddress((void**)&bufH,     g_bufH);
    cudaGetSymbolAddress((void**)&bufG,     g_bufG);
    cudaGetSymbolAddress((void**)&bufX,     g_bufX);

    int nb = (n + 255) / 256;
    int eb = (e + 255) / 256;
    int sb = (n + TILE - 1) / TILE;   // scan blocks (98)

    // CSR build (shared by both layers)
    zero_kernel<<<nb, 256>>>(cnt, cursor, n);
    hist_kernel<<<eb, 256>>>(ei, cnt, e, n);
    dinv_kernel<<<nb, 256>>>(cnt, dinv, n);
    partial_kernel<<<sb, 256>>>(cnt, blocksum, n);
    scan_sums_kernel<<<1, 128>>>(blocksum, rowptr, sb, n);
    write_rowptr_kernel<<<sb, 256>>>(cnt, blocksum, rowptr, n);
    fill_kernel<<<eb, 256>>>(ei, rowptr, cursor, csrsrc, e, n);

    int gemm_blocks   = (n + 63) / 64;
    int gather_blocks = (int)(((long long)n * 32 + 255) / 256);

    // layer 1
    gemm_scaled_kernel<<<gemm_blocks, 256>>>(x, W1, dinv, bufH, n);
    gather_kernel<true><<<gather_blocks, 256>>>(rowptr, csrsrc, bufH, dinv, b1, bufX, n);

    // layer 2
    gemm_scaled_kernel<<<gemm_blocks, 256>>>(bufX, W2, dinv, bufH, n);
    gather_kernel<false><<<gather_blocks, 256>>>(rowptr, csrsrc, bufH, dinv, b2, bufG, n);

    // normalize + decode + log_softmax
    final_kernel<<<(n + 7) / 8, 256>>>(bufG, Wd, bd, out_logits, out_emb, n);
}